// round 16
// baseline (speedup 1.0000x reference)
#include <cuda_runtime.h>
#include <cuda_bf16.h>
#include <cstdint>

// INT4 symmetric grouped dequant — warp-contiguous 256-bit stores.
//   packed: TOTAL/2 int32 (one byte each, two nibbles: low = even elem, high = odd)
//   scale:  (4096, 86) fp32, group size 128
//   out:    fp32, out[i] = (nibble - 8) * scale[i/128]
//
// R4's STG.E.256 had lane L at stride 64B -> 16 half-covered 128B lines
// per instruction (2x L1tex store wavefront amplification). Remap:
//   warp W covers output floats [512W, 512W+512)  (2KB, full lines)
//   lane L: load1 = int4 packed_int4[64W + L]        (contig 512B/warp)
//           load2 = int4 packed_int4[64W + 32 + L]   (next 512B)
//           store1 = v8 out[512W + 8L]               (contig 1KB/warp, full lines)
//           store2 = v8 out[512W + 256 + 8L]
// Each 16B input (4 packed ints -> 8 codes) produces exactly its 32B output.
// Scale group = float_index >> 7.

#define N_PACKED   22544384                  // TOTAL/2 int32s
#define N_INT4     (N_PACKED / 4)            // 5,636,096 int4 tiles
#define THREADS    256
#define BLOCKS     (N_INT4 / (THREADS * 2))  // 11,008 exact (2 int4 loads/thread)

__device__ __forceinline__ void dequant8(const int4 p, const float s, float* f)
{
    f[0] = (float)(( p.x       & 15) - 8) * s;
    f[1] = (float)(((p.x >> 4) & 15) - 8) * s;
    f[2] = (float)(( p.y       & 15) - 8) * s;
    f[3] = (float)(((p.y >> 4) & 15) - 8) * s;
    f[4] = (float)(( p.z       & 15) - 8) * s;
    f[5] = (float)(((p.z >> 4) & 15) - 8) * s;
    f[6] = (float)(( p.w       & 15) - 8) * s;
    f[7] = (float)(((p.w >> 4) & 15) - 8) * s;
}

__global__ void __launch_bounds__(THREADS)
int4_dequant_kernel(const int4* __restrict__ packed4,
                    const float* __restrict__ scale,
                    float* __restrict__ out)
{
    const int t    = blockIdx.x * THREADS + threadIdx.x;
    const int W    = t >> 5;                  // global warp id
    const int L    = t & 31;                  // lane
    const int ibase = W * 64 + L;             // int4 index, load1

    // Front-batched loads: each contiguous 512B per warp
    const int4 p0 = __ldcs(&packed4[ibase]);
    const int4 p1 = __ldcs(&packed4[ibase + 32]);

    const int f0 = W * 512 + 8 * L;           // output float index, store1
    const int f1 = f0 + 256;                  //                     store2
    const float s0 = __ldg(&scale[f0 >> 7]);
    const float s1 = __ldg(&scale[f1 >> 7]);

    float a[8], b[8];
    dequant8(p0, s0, a);
    dequant8(p1, s1, b);

    asm volatile(
        "st.global.cs.v8.f32 [%0], {%1,%2,%3,%4,%5,%6,%7,%8};"
        :: "l"(out + f0),
           "f"(a[0]), "f"(a[1]), "f"(a[2]), "f"(a[3]),
           "f"(a[4]), "f"(a[5]), "f"(a[6]), "f"(a[7])
        : "memory");
    asm volatile(
        "st.global.cs.v8.f32 [%0], {%1,%2,%3,%4,%5,%6,%7,%8};"
        :: "l"(out + f1),
           "f"(b[0]), "f"(b[1]), "f"(b[2]), "f"(b[3]),
           "f"(b[4]), "f"(b[5]), "f"(b[6]), "f"(b[7])
        : "memory");
}

extern "C" void kernel_launch(void* const* d_in, const int* in_sizes, int n_in,
                              void* d_out, int out_size)
{
    const int4*  packed4 = (const int4*)d_in[0];
    const float* scale   = (const float*)d_in[1];
    float*       out     = (float*)d_out;

    int4_dequant_kernel<<<BLOCKS, THREADS>>>(packed4, scale, out);
}